// round 2
// baseline (speedup 1.0000x reference)
#include <cuda_runtime.h>
#include <math.h>

#define BB 256
#define TT 256
#define DD 128
#define HH 512
#define G3 1536
#define G6 3072
#define GRID_CTAS 148

// Persistent scratch (device globals — no allocation allowed)
__device__ float g_h[BB*HH];
__device__ float g_hp[BB*HH];
__device__ float g_gh0[BB*G3];
__device__ float g_gi0[BB*G3];
__device__ float g_g1[BB*G6];
__device__ float g_imp[BB*DD];
__device__ unsigned g_bar;

__global__ void init_kernel() {
    unsigned idx = blockIdx.x * blockDim.x + threadIdx.x;
    if (idx == 0) g_bar = 0u;
    unsigned stride = gridDim.x * blockDim.x;
    for (unsigned i = idx; i < BB*HH; i += stride) g_h[i] = 0.f;
}

// Monotonic-counter grid barrier. Writers fence before arriving; readers use
// __ldcg on shared state, so no L1 staleness.
__device__ __forceinline__ void grid_barrier(unsigned &target) {
    __syncthreads();
    target += gridDim.x;
    if (threadIdx.x == 0) {
        __threadfence();
        atomicAdd(&g_bar, 1u);
        while (*((volatile unsigned*)&g_bar) < target) { }
    }
    __syncthreads();
}

__device__ __forceinline__ float sigf(float x) { return 1.f / (1.f + expf(-x)); }

// 64x64 output tile, 256 threads, 4x4 per-thread micro-tile, K-chunk 32.
// A is recurrent state (read via __ldcg); weight rows via wrow(n) (read via __ldg).
template<int KDIM, class WROW, class EPI>
__device__ __forceinline__ void run_gemm(float (*As)[68], float (*Bs)[68],
                                         const float* A, int lda, int Ntiles,
                                         WROW wrow, EPI epi)
{
    const int tid = threadIdx.x;
    const int ty = tid >> 4, tx = tid & 15;
    const int lr = tid >> 3;   // 0..31
    const int kq = tid & 7;    // 0..7
    const int total = 4 * Ntiles;
    for (int tile = blockIdx.x; tile < total; tile += gridDim.x) {
        const int mt = tile / Ntiles, nt = tile % Ntiles;
        const int m0 = mt * 64, n0 = nt * 64;
        float c[4][4];
        #pragma unroll
        for (int i = 0; i < 4; i++)
            #pragma unroll
            for (int j = 0; j < 4; j++) c[i][j] = 0.f;

        const float* a0 = A + (size_t)(m0 + lr) * lda;
        const float* a1 = A + (size_t)(m0 + lr + 32) * lda;
        const float* w0 = wrow(n0 + lr);
        const float* w1 = wrow(n0 + lr + 32);

        for (int k0 = 0; k0 < KDIM; k0 += 32) {
            float4 av0 = __ldcg((const float4*)(a0 + k0 + kq*4));
            float4 av1 = __ldcg((const float4*)(a1 + k0 + kq*4));
            float4 bv0 = __ldg((const float4*)(w0 + k0 + kq*4));
            float4 bv1 = __ldg((const float4*)(w1 + k0 + kq*4));
            __syncthreads();
            int kr = kq * 4;
            As[kr+0][lr]    = av0.x; As[kr+1][lr]    = av0.y;
            As[kr+2][lr]    = av0.z; As[kr+3][lr]    = av0.w;
            As[kr+0][lr+32] = av1.x; As[kr+1][lr+32] = av1.y;
            As[kr+2][lr+32] = av1.z; As[kr+3][lr+32] = av1.w;
            Bs[kr+0][lr]    = bv0.x; Bs[kr+1][lr]    = bv0.y;
            Bs[kr+2][lr]    = bv0.z; Bs[kr+3][lr]    = bv0.w;
            Bs[kr+0][lr+32] = bv1.x; Bs[kr+1][lr+32] = bv1.y;
            Bs[kr+2][lr+32] = bv1.z; Bs[kr+3][lr+32] = bv1.w;
            __syncthreads();
            #pragma unroll
            for (int kk = 0; kk < 32; kk++) {
                float4 a = *(const float4*)(&As[kk][ty*4]);
                float4 b = *(const float4*)(&Bs[kk][tx*4]);
                c[0][0] = fmaf(a.x, b.x, c[0][0]); c[0][1] = fmaf(a.x, b.y, c[0][1]);
                c[0][2] = fmaf(a.x, b.z, c[0][2]); c[0][3] = fmaf(a.x, b.w, c[0][3]);
                c[1][0] = fmaf(a.y, b.x, c[1][0]); c[1][1] = fmaf(a.y, b.y, c[1][1]);
                c[1][2] = fmaf(a.y, b.z, c[1][2]); c[1][3] = fmaf(a.y, b.w, c[1][3]);
                c[2][0] = fmaf(a.z, b.x, c[2][0]); c[2][1] = fmaf(a.z, b.y, c[2][1]);
                c[2][2] = fmaf(a.z, b.z, c[2][2]); c[2][3] = fmaf(a.z, b.w, c[2][3]);
                c[3][0] = fmaf(a.w, b.x, c[3][0]); c[3][1] = fmaf(a.w, b.y, c[3][1]);
                c[3][2] = fmaf(a.w, b.z, c[3][2]); c[3][3] = fmaf(a.w, b.w, c[3][3]);
            }
        }
        epi(c, m0 + ty*4, n0 + tx*4);
    }
}

__global__ void __launch_bounds__(256) brits_kernel(
    const float* __restrict__ X,     const float* __restrict__ Msk,
    const float* __restrict__ W_ih0, const float* __restrict__ W_hh0,
    const float* __restrict__ b_ih0, const float* __restrict__ b_hh0,
    const float* __restrict__ W_ih1, const float* __restrict__ W_hh1,
    const float* __restrict__ b_ih1, const float* __restrict__ b_hh1,
    const float* __restrict__ W_out, const float* __restrict__ b_out,
    float* __restrict__ out)
{
    __shared__ __align__(16) float As[32][68];
    __shared__ __align__(16) float Bs[32][68];

    float* pre_o = out;
    float* out_o = out + (size_t)BB*TT*DD;
    float* hf_o  = out + (size_t)2*BB*TT*DD;
    float* hid_o = hf_o + (size_t)BB*HH;

    unsigned target = 0;
    const int gs   = gridDim.x * blockDim.x;
    const int gtid = blockIdx.x * blockDim.x + threadIdx.x;

    for (int t = 0; t < TT; t++) {
        // ---- Phase A: gh0 = h@W_hh0^T + b_hh0 ; est = h@W_out^T + b_out ; imputed ----
        {
            auto wrow = [&](int n) -> const float* {
                return (n < G3) ? (W_hh0 + (size_t)n * HH) : (W_out + (size_t)(n - G3) * HH);
            };
            auto epi = [&](float (&c)[4][4], int mb, int nb) {
                #pragma unroll
                for (int i = 0; i < 4; i++) {
                    int b = mb + i;
                    #pragma unroll
                    for (int j = 0; j < 4; j++) {
                        int n = nb + j;
                        float v = c[i][j];
                        if (n < G3) {
                            g_gh0[b*G3 + n] = v + b_hh0[n];
                        } else {
                            int d = n - G3;
                            float est = v + b_out[d];
                            int io = (b*TT + t)*DD + d;
                            pre_o[io] = est;
                            float mv = Msk[io];
                            float imp = est + mv * (X[io] - est);
                            g_imp[b*DD + d] = imp;
                            if (t > 0) out_o[io - DD] = imp;   // position t-1
                        }
                    }
                }
            };
            run_gemm<HH>(As, Bs, g_h, HH, 26, wrow, epi);
        }
        grid_barrier(target);

        // ---- Phase B1: gi0 = imputed @ W_ih0^T ----
        {
            auto wrow = [&](int n) -> const float* { return W_ih0 + (size_t)n * DD; };
            auto epi = [&](float (&c)[4][4], int mb, int nb) {
                #pragma unroll
                for (int i = 0; i < 4; i++)
                    #pragma unroll
                    for (int j = 0; j < 4; j++)
                        g_gi0[(mb+i)*G3 + nb + j] = c[i][j];
            };
            run_gemm<DD>(As, Bs, g_imp, DD, 24, wrow, epi);
        }
        grid_barrier(target);

        // ---- B2: gates of GRU cell 0 → h' ----
        for (int idx = gtid; idx < BB*HH; idx += gs) {
            int b = idx >> 9, j = idx & 511;
            int base = b*G3 + j;
            float gr = __ldcg(&g_gi0[base])        + b_ih0[j]        + __ldcg(&g_gh0[base]);
            float gz = __ldcg(&g_gi0[base + HH])   + b_ih0[j + HH]   + __ldcg(&g_gh0[base + HH]);
            float gn = __ldcg(&g_gi0[base + 2*HH]) + b_ih0[j + 2*HH];
            float hn = __ldcg(&g_gh0[base + 2*HH]);                 // includes b_hh0
            float r = sigf(gr), z = sigf(gz);
            float nn = tanhf(gn + r * hn);
            float hold = __ldcg(&g_h[idx]);
            g_hp[idx] = (1.f - z) * nn + z * hold;
        }
        grid_barrier(target);

        // ---- Phase C1: [gi1 | gh1] = h' @ [W_ih1 ; W_hh1]^T ----
        {
            auto wrow = [&](int n) -> const float* {
                return (n < G3) ? (W_ih1 + (size_t)n * HH) : (W_hh1 + (size_t)(n - G3) * HH);
            };
            auto epi = [&](float (&c)[4][4], int mb, int nb) {
                #pragma unroll
                for (int i = 0; i < 4; i++)
                    #pragma unroll
                    for (int j = 0; j < 4; j++)
                        g_g1[(mb+i)*G6 + nb + j] = c[i][j];
            };
            run_gemm<HH>(As, Bs, g_hp, HH, 48, wrow, epi);
        }
        grid_barrier(target);

        // ---- C2: gates of GRU cell 1 → h ; emit hidden_state_collector ----
        for (int idx = gtid; idx < BB*HH; idx += gs) {
            int b = idx >> 9, j = idx & 511;
            int base = b*G6 + j;
            float ar = __ldcg(&g_g1[base])             + b_ih1[j]
                     + __ldcg(&g_g1[base + G3])        + b_hh1[j];
            float az = __ldcg(&g_g1[base + HH])        + b_ih1[j + HH]
                     + __ldcg(&g_g1[base + G3 + HH])   + b_hh1[j + HH];
            float an = __ldcg(&g_g1[base + 2*HH])      + b_ih1[j + 2*HH];
            float hn = __ldcg(&g_g1[base + G3 + 2*HH]) + b_hh1[j + 2*HH];
            float r = sigf(ar), z = sigf(az);
            float nn = tanhf(an + r * hn);
            float hpv = __ldcg(&g_hp[idx]);
            float hnew = (1.f - z) * nn + z * hpv;
            g_h[idx] = hnew;
            hid_o[((size_t)b*TT + t)*HH + j] = hnew;
        }
        grid_barrier(target);
    }

    // ---- Final: est(h_final) → output_collector[:, T-1, :] ----
    {
        auto wrow = [&](int n) -> const float* { return W_out + (size_t)n * HH; };
        auto epi = [&](float (&c)[4][4], int mb, int nb) {
            #pragma unroll
            for (int i = 0; i < 4; i++) {
                int b = mb + i;
                #pragma unroll
                for (int j = 0; j < 4; j++) {
                    int d = nb + j;
                    out_o[((size_t)b*TT + (TT-1))*DD + d] = c[i][j] + b_out[d];
                }
            }
        };
        run_gemm<HH>(As, Bs, g_h, HH, 2, wrow, epi);
    }
    // h_final
    for (int idx = gtid; idx < BB*HH; idx += gs)
        hf_o[idx] = __ldcg(&g_h[idx]);
}

extern "C" void kernel_launch(void* const* d_in, const int* in_sizes, int n_in,
                              void* d_out, int out_size) {
    const float* X     = (const float*)d_in[0];
    const float* Msk   = (const float*)d_in[1];
    const float* W_ih0 = (const float*)d_in[2];
    const float* W_hh0 = (const float*)d_in[3];
    const float* b_ih0 = (const float*)d_in[4];
    const float* b_hh0 = (const float*)d_in[5];
    const float* W_ih1 = (const float*)d_in[6];
    const float* W_hh1 = (const float*)d_in[7];
    const float* b_ih1 = (const float*)d_in[8];
    const float* b_hh1 = (const float*)d_in[9];
    const float* W_out = (const float*)d_in[10];
    const float* b_out = (const float*)d_in[11];
    float* out = (float*)d_out;

    init_kernel<<<64, 256>>>();
    brits_kernel<<<GRID_CTAS, 256>>>(X, Msk, W_ih0, W_hh0, b_ih0, b_hh0,
                                     W_ih1, W_hh1, b_ih1, b_hh1, W_out, b_out, out);
}

// round 3
// speedup vs baseline: 1.9856x; 1.9856x over previous
#include <cuda_runtime.h>
#include <math.h>

#define BB 256
#define TT 256
#define DD 128
#define HH 512
#define G3 1536
#define G6 3072
#define NCTA 148
typedef unsigned long long ull;

__device__ float g_h[BB*HH];
__device__ float g_hp[BB*HH];
__device__ float g_gh0[BB*G3];
__device__ float g_gi0[BB*G3];
__device__ float g_g1[BB*G6];
__device__ float g_imp[BB*DD];
__device__ unsigned g_bar;

__global__ void init_kernel() {
    unsigned idx = blockIdx.x * blockDim.x + threadIdx.x;
    if (idx == 0) g_bar = 0u;
    for (unsigned i = idx; i < BB*HH; i += gridDim.x * blockDim.x) g_h[i] = 0.f;
}

__device__ __forceinline__ void grid_barrier(unsigned &target) {
    __syncthreads();
    target += gridDim.x;
    if (threadIdx.x == 0) {
        __threadfence();
        atomicAdd(&g_bar, 1u);
        int sp = 0;
        while (*((volatile unsigned*)&g_bar) < target)
            if (++sp > 64) __nanosleep(40);
    }
    __syncthreads();
}

__device__ __forceinline__ float sigf(float x) { return 1.f / (1.f + expf(-x)); }
__device__ __forceinline__ ull pack2(float lo, float hi) {
    ull r; asm("mov.b64 %0, {%1, %2};" : "=l"(r) : "f"(lo), "f"(hi)); return r;
}
__device__ __forceinline__ void unpack2(ull v, float &lo, float &hi) {
    asm("mov.b64 {%0, %1}, %2;" : "=f"(lo), "=f"(hi) : "l"(v));
}
__device__ __forceinline__ ull fma2(ull a, ull b, ull c) {
    ull d; asm("fma.rn.f32x2 %0, %1, %2, %3;" : "=l"(d) : "l"(a), "l"(b), "l"(c)); return d;
}

// 64 x (16*TNW) tile, 256 threads, micro 4xTNW via fma.rn.f32x2,
// K-chunk 32, double-buffered smem, one __syncthreads per chunk.
template<int KDIM, int TNW, class AROW, class WROW, class EPI>
__device__ __forceinline__ void gemm(float* smA, float* smB, int m0, int n0,
                                     AROW arow, WROW wrow, EPI epi)
{
    constexpr int TN = 16 * TNW, ASTR = 68, BSTR = TN + 4, NB = TN / 32, NC = KDIM / 32;
    const int tid = threadIdx.x;
    const int r = tid >> 3, c4 = (tid & 7) << 2;
    const int ty = tid >> 4, tx = tid & 15;

    const float* a0 = arow(m0 + r);
    const float* a1 = arow(m0 + r + 32);
    const float* w[NB];
    #pragma unroll
    for (int g = 0; g < NB; g++) w[g] = wrow(n0 + r + 32*g);

    ull acc[4][TNW/2];
    #pragma unroll
    for (int i = 0; i < 4; i++)
        #pragma unroll
        for (int j = 0; j < TNW/2; j++) acc[i][j] = 0ull;

    float4 pa0 = __ldcg((const float4*)(a0 + c4));
    float4 pa1 = __ldcg((const float4*)(a1 + c4));
    float4 pb[NB];
    #pragma unroll
    for (int g = 0; g < NB; g++) pb[g] = __ldg((const float4*)(w[g] + c4));

    {   // store chunk 0 into buffer 0
        float* A0 = smA; float* B0 = smB;
        A0[(c4+0)*ASTR + r] = pa0.x; A0[(c4+1)*ASTR + r] = pa0.y;
        A0[(c4+2)*ASTR + r] = pa0.z; A0[(c4+3)*ASTR + r] = pa0.w;
        A0[(c4+0)*ASTR + r+32] = pa1.x; A0[(c4+1)*ASTR + r+32] = pa1.y;
        A0[(c4+2)*ASTR + r+32] = pa1.z; A0[(c4+3)*ASTR + r+32] = pa1.w;
        #pragma unroll
        for (int g = 0; g < NB; g++) {
            B0[(c4+0)*BSTR + r+32*g] = pb[g].x; B0[(c4+1)*BSTR + r+32*g] = pb[g].y;
            B0[(c4+2)*BSTR + r+32*g] = pb[g].z; B0[(c4+3)*BSTR + r+32*g] = pb[g].w;
        }
    }
    __syncthreads();

    for (int ch = 0; ch < NC; ch++) {
        if (ch + 1 < NC) {
            const int k = (ch + 1) * 32;
            pa0 = __ldcg((const float4*)(a0 + k + c4));
            pa1 = __ldcg((const float4*)(a1 + k + c4));
            #pragma unroll
            for (int g = 0; g < NB; g++) pb[g] = __ldg((const float4*)(w[g] + k + c4));
        }
        const float* Ac = smA + (ch & 1) * 32 * ASTR;
        const float* Bc = smB + (ch & 1) * 32 * BSTR;
        #pragma unroll
        for (int kk = 0; kk < 32; kk++) {
            float4 a = *(const float4*)(Ac + kk*ASTR + ty*4);
            ull bv[TNW/2];
            #pragma unroll
            for (int j = 0; j < TNW/2; j++)
                bv[j] = *(const ull*)(Bc + kk*BSTR + tx*TNW + 2*j);
            ull ap[4] = { pack2(a.x,a.x), pack2(a.y,a.y), pack2(a.z,a.z), pack2(a.w,a.w) };
            #pragma unroll
            for (int i = 0; i < 4; i++)
                #pragma unroll
                for (int j = 0; j < TNW/2; j++)
                    acc[i][j] = fma2(ap[i], bv[j], acc[i][j]);
        }
        if (ch + 1 < NC) {
            float* A0 = smA + ((ch+1) & 1) * 32 * ASTR;
            float* B0 = smB + ((ch+1) & 1) * 32 * BSTR;
            A0[(c4+0)*ASTR + r] = pa0.x; A0[(c4+1)*ASTR + r] = pa0.y;
            A0[(c4+2)*ASTR + r] = pa0.z; A0[(c4+3)*ASTR + r] = pa0.w;
            A0[(c4+0)*ASTR + r+32] = pa1.x; A0[(c4+1)*ASTR + r+32] = pa1.y;
            A0[(c4+2)*ASTR + r+32] = pa1.z; A0[(c4+3)*ASTR + r+32] = pa1.w;
            #pragma unroll
            for (int g = 0; g < NB; g++) {
                B0[(c4+0)*BSTR + r+32*g] = pb[g].x; B0[(c4+1)*BSTR + r+32*g] = pb[g].y;
                B0[(c4+2)*BSTR + r+32*g] = pb[g].z; B0[(c4+3)*BSTR + r+32*g] = pb[g].w;
            }
        }
        __syncthreads();
    }

    float c[4][TNW];
    #pragma unroll
    for (int i = 0; i < 4; i++)
        #pragma unroll
        for (int j = 0; j < TNW/2; j++)
            unpack2(acc[i][j], c[i][2*j], c[i][2*j+1]);
    epi(c, m0 + ty*4, n0 + tx*TNW);
}

__global__ void __launch_bounds__(256, 1) brits_kernel(
    const float* __restrict__ X,     const float* __restrict__ Msk,
    const float* __restrict__ W_ih0, const float* __restrict__ W_hh0,
    const float* __restrict__ b_ih0, const float* __restrict__ b_hh0,
    const float* __restrict__ W_ih1, const float* __restrict__ W_hh1,
    const float* __restrict__ b_ih1, const float* __restrict__ b_hh1,
    const float* __restrict__ W_out, const float* __restrict__ b_out,
    float* __restrict__ out)
{
    __shared__ __align__(16) float smem[2*32*68 + 2*32*100];
    float* smA = smem;
    float* smB = smem + 2*32*68;

    float* pre_o = out;
    float* out_o = out + (size_t)BB*TT*DD;
    float* hf_o  = out + (size_t)2*BB*TT*DD;
    float* hid_o = hf_o + (size_t)BB*HH;

    unsigned target = 0;
    const int gs   = gridDim.x * blockDim.x;
    const int gtid = blockIdx.x * blockDim.x + threadIdx.x;
    const int bx   = blockIdx.x;

    for (int t = 0; t < TT; t++) {
        // A: [gh0 | est] = h @ [W_hh0 ; W_out]^T, 104 tiles 64x64, K=512
        if (bx < 104) {
            const int m0 = (bx / 26) * 64, n0 = (bx % 26) * 64;
            auto arow = [&](int m) { return g_h + (size_t)m * HH; };
            auto wrow = [&](int n) {
                return (n < G3) ? (W_hh0 + (size_t)n * HH) : (W_out + (size_t)(n - G3) * HH);
            };
            auto epi = [&](float (&c)[4][4], int mb, int nb) {
                #pragma unroll
                for (int i = 0; i < 4; i++) {
                    int b = mb + i;
                    #pragma unroll
                    for (int j = 0; j < 4; j++) {
                        int n = nb + j; float v = c[i][j];
                        if (n < G3) g_gh0[b*G3 + n] = v + b_hh0[n];
                        else {
                            int d = n - G3;
                            float est = v + b_out[d];
                            int io = (b*TT + t)*DD + d;
                            pre_o[io] = est;
                            float imp = est + Msk[io] * (X[io] - est);
                            g_imp[b*DD + d] = imp;
                            if (t > 0) out_o[io - DD] = imp;
                        }
                    }
                }
            };
            gemm<HH, 4>(smA, smB, m0, n0, arow, wrow, epi);
        }
        grid_barrier(target);

        // B1: gi0 = imputed @ W_ih0^T, 96 tiles 64x64, K=128
        if (bx < 96) {
            const int m0 = (bx / 24) * 64, n0 = (bx % 24) * 64;
            auto arow = [&](int m) { return g_imp + (size_t)m * DD; };
            auto wrow = [&](int n) { return W_ih0 + (size_t)n * DD; };
            auto epi = [&](float (&c)[4][4], int mb, int nb) {
                #pragma unroll
                for (int i = 0; i < 4; i++)
                    #pragma unroll
                    for (int j = 0; j < 4; j++)
                        g_gi0[(mb+i)*G3 + nb + j] = c[i][j];
            };
            gemm<DD, 4>(smA, smB, m0, n0, arow, wrow, epi);
        }
        grid_barrier(target);

        // B2: cell-0 gates -> h'
        for (int idx = gtid; idx < BB*HH; idx += gs) {
            int b = idx >> 9, j = idx & 511;
            int base = b*G3 + j;
            float gr = __ldcg(&g_gi0[base])        + b_ih0[j]        + __ldcg(&g_gh0[base]);
            float gz = __ldcg(&g_gi0[base + HH])   + b_ih0[j + HH]   + __ldcg(&g_gh0[base + HH]);
            float gn = __ldcg(&g_gi0[base + 2*HH]) + b_ih0[j + 2*HH];
            float hn = __ldcg(&g_gh0[base + 2*HH]);
            float rr = sigf(gr), z = sigf(gz);
            float nn = tanhf(gn + rr * hn);
            g_hp[idx] = (1.f - z) * nn + z * __ldcg(&g_h[idx]);
        }
        grid_barrier(target);

        // C1: [gi1 | gh1] = h' @ [W_ih1 ; W_hh1]^T, 128 tiles 64x96, K=512
        if (bx < 128) {
            const int m0 = (bx / 32) * 64, n0 = (bx % 32) * 96;
            auto arow = [&](int m) { return g_hp + (size_t)m * HH; };
            auto wrow = [&](int n) {
                return (n < G3) ? (W_ih1 + (size_t)n * HH) : (W_hh1 + (size_t)(n - G3) * HH);
            };
            auto epi = [&](float (&c)[4][6], int mb, int nb) {
                #pragma unroll
                for (int i = 0; i < 4; i++)
                    #pragma unroll
                    for (int j = 0; j < 6; j++)
                        g_g1[(mb+i)*G6 + nb + j] = c[i][j];
            };
            gemm<HH, 6>(smA, smB, m0, n0, arow, wrow, epi);
        }
        grid_barrier(target);

        // C2: cell-1 gates -> h ; emit hidden states
        for (int idx = gtid; idx < BB*HH; idx += gs) {
            int b = idx >> 9, j = idx & 511;
            int base = b*G6 + j;
            float ar = __ldcg(&g_g1[base])             + b_ih1[j]
                     + __ldcg(&g_g1[base + G3])        + b_hh1[j];
            float az = __ldcg(&g_g1[base + HH])        + b_ih1[j + HH]
                     + __ldcg(&g_g1[base + G3 + HH])   + b_hh1[j + HH];
            float an = __ldcg(&g_g1[base + 2*HH])      + b_ih1[j + 2*HH];
            float hn = __ldcg(&g_g1[base + G3 + 2*HH]) + b_hh1[j + 2*HH];
            float rr = sigf(ar), z = sigf(az);
            float nn = tanhf(an + rr * hn);
            float hnew = (1.f - z) * nn + z * __ldcg(&g_hp[idx]);
            g_h[idx] = hnew;
            hid_o[((size_t)b*TT + t)*HH + j] = hnew;
        }
        grid_barrier(target);
    }

    // Final est(h_final) -> output_collector[:, T-1, :]
    if (bx < 8) {
        const int m0 = (bx / 2) * 64, n0 = (bx % 2) * 64;
        auto arow = [&](int m) { return g_h + (size_t)m * HH; };
        auto wrow = [&](int n) { return W_out + (size_t)n * HH; };
        auto epi = [&](float (&c)[4][4], int mb, int nb) {
            #pragma unroll
            for (int i = 0; i < 4; i++)
                #pragma unroll
                for (int j = 0; j < 4; j++)
                    out_o[((size_t)(mb+i)*TT + (TT-1))*DD + nb + j] = c[i][j] + b_out[nb + j];
        };
        gemm<HH, 4>(smA, smB, m0, n0, arow, wrow, epi);
    }
    for (int idx = gtid; idx < BB*HH; idx += gs)
        hf_o[idx] = __ldcg(&g_h[idx]);
}

extern "C" void kernel_launch(void* const* d_in, const int* in_sizes, int n_in,
                              void* d_out, int out_size) {
    const float* X     = (const float*)d_in[0];
    const float* Msk   = (const float*)d_in[1];
    const float* W_ih0 = (const float*)d_in[2];
    const float* W_hh0 = (const float*)d_in[3];
    const float* b_ih0 = (const float*)d_in[4];
    const float* b_hh0 = (const float*)d_in[5];
    const float* W_ih1 = (const float*)d_in[6];
    const float* W_hh1 = (const float*)d_in[7];
    const float* b_ih1 = (const float*)d_in[8];
    const float* b_hh1 = (const float*)d_in[9];
    const float* W_out = (const float*)d_in[10];
    const float* b_out = (const float*)d_in[11];

    init_kernel<<<64, 256>>>();
    brits_kernel<<<NCTA, 256>>>(X, Msk, W_ih0, W_hh0, b_ih0, b_hh0,
                                W_ih1, W_hh1, b_ih1, b_hh1, W_out, b_out, (float*)d_out);
}